// round 3
// baseline (speedup 1.0000x reference)
#include <cuda_runtime.h>
#include <math.h>

#define NN 50000
#define NE 800000
#define CDIM 128
#define NLAYER 4
#define NCLASS 40

// ---------------- scratch (device globals; no allocation allowed) ----------------
__device__ int   g_is64;
__device__ int   g_deg[NN];
__device__ int   g_fill[NN];
__device__ int   g_rowptr[NN + 1];
__device__ float g_dinv[NN];
__device__ int   g_col[NE];
__device__ __align__(16) float g_ew[NE];
__device__ __align__(16) float g_hW[(size_t)NN * CDIM];
__device__ __align__(16) float g_H[(size_t)NLAYER * NN * CDIM];
__device__ __align__(16) float g_scores[(size_t)NN * NLAYER];

// ---------------- edge dtype detection ----------------
// int64 edge data: every value in [0, NN). int32 data read as int64 packs the
// NEXT index in the high 32 bits -> value >= 2^32 almost surely. 8 samples.
__global__ void detect_kernel(const void* ei) {
    const long long* p = (const long long*)ei;
    int ok = 1;
    for (int i = 0; i < 8; ++i) {
        long long v = p[i];
        if (v < 0 || v >= NN) ok = 0;
    }
    g_is64 = ok;
}

__device__ __forceinline__ int edge_src(const void* ei, int e) {
    return g_is64 ? (int)((const long long*)ei)[e] : ((const int*)ei)[e];
}
__device__ __forceinline__ int edge_dst(const void* ei, int e) {
    return g_is64 ? (int)((const long long*)ei)[NE + e] : ((const int*)ei)[NE + e];
}

// ---------------- CSR build ----------------
__global__ void zero_kernel() {
    int i = blockIdx.x * blockDim.x + threadIdx.x;
    if (i < NN) { g_deg[i] = 0; g_fill[i] = 0; }
}

__global__ void hist_kernel(const void* __restrict__ ei) {
    int e = blockIdx.x * blockDim.x + threadIdx.x;
    if (e < NE) {
        int d = edge_dst(ei, e);
        if ((unsigned)d < NN) atomicAdd(&g_deg[d], 1);
    }
}

// single-block inclusive scan over 50000 ints (Hillis-Steele per 1024 chunk + carry)
__global__ void scan_dinv_kernel() {
    __shared__ int sm[1024];
    __shared__ int carry;
    int tid = threadIdx.x;
    if (tid == 0) { carry = 0; g_rowptr[0] = 0; }
    __syncthreads();
    for (int base = 0; base < NN; base += 1024) {
        int i = base + tid;
        int v = (i < NN) ? g_deg[i] : 0;
        if (i < NN) g_dinv[i] = rsqrtf(1.0f + (float)v);
        sm[tid] = v;
        __syncthreads();
        for (int off = 1; off < 1024; off <<= 1) {
            int t = (tid >= off) ? sm[tid - off] : 0;
            __syncthreads();
            sm[tid] += t;
            __syncthreads();
        }
        if (i < NN) g_rowptr[i + 1] = carry + sm[tid];
        __syncthreads();
        if (tid == 1023) carry += sm[tid];
        __syncthreads();
    }
}

__global__ void scatter_kernel(const void* __restrict__ ei) {
    int e = blockIdx.x * blockDim.x + threadIdx.x;
    if (e < NE) {
        int s = edge_src(ei, e);
        int d = edge_dst(ei, e);
        if ((unsigned)s < NN && (unsigned)d < NN) {
            int pos = g_rowptr[d] + atomicAdd(&g_fill[d], 1);
            g_col[pos] = s;
            g_ew[pos]  = g_dinv[s] * g_dinv[d];
        }
    }
}

// ---------------- GEMM: C[m][n] = sum_k A[m][k]*B[k][n], A [NN x 128], B [128 x 128]
// ATT==0: A = (use_x ? x : g_H[l-1]), C = g_hW
// ATT==1: A = g_H[l]; score = sum_n tanh(C[m][n]) * avec[n] -> g_scores[:, l]
template<int ATT>
__global__ __launch_bounds__(256) void gemm_kernel(const float* __restrict__ x,
                                                   const float* __restrict__ B,
                                                   const float* __restrict__ avec,
                                                   int l, int use_x) {
    __shared__ float As[128][33];   // [m][k], pad 33
    __shared__ float Bs[32][128];   // [k][n]
    const float* A;
    if (ATT == 1)       A = g_H + (size_t)l * NN * CDIM;
    else if (use_x)     A = x;
    else                A = g_H + (size_t)(l - 1) * NN * CDIM;
    float* C = g_hW;

    int tid = threadIdx.x;
    int m0 = blockIdx.x * 128;
    int tx = tid & 15, ty = tid >> 4;

    float acc[8][8];
#pragma unroll
    for (int r = 0; r < 8; ++r)
#pragma unroll
        for (int j = 0; j < 8; ++j) acc[r][j] = 0.f;

    for (int kc = 0; kc < 128; kc += 32) {
        __syncthreads();
#pragma unroll
        for (int it = 0; it < 4; ++it) {           // A chunk: 128 rows x 32 k
            int idx = it * 256 + tid;
            int m = idx >> 3, kq = idx & 7;
            int row = m0 + m;
            float4 v = make_float4(0.f, 0.f, 0.f, 0.f);
            if (row < NN) v = *(const float4*)(A + (size_t)row * 128 + kc + kq * 4);
            As[m][kq * 4 + 0] = v.x; As[m][kq * 4 + 1] = v.y;
            As[m][kq * 4 + 2] = v.z; As[m][kq * 4 + 3] = v.w;
        }
#pragma unroll
        for (int it = 0; it < 4; ++it) {           // B chunk: 32 k x 128 n
            int idx = it * 256 + tid;
            int k = idx >> 5, c = idx & 31;
            *(float4*)(&Bs[k][c * 4]) = *(const float4*)(B + (size_t)(kc + k) * 128 + c * 4);
        }
        __syncthreads();
#pragma unroll
        for (int kk = 0; kk < 32; ++kk) {
            float b[8];
            float4 b0 = *(const float4*)(&Bs[kk][tx * 8]);
            float4 b1 = *(const float4*)(&Bs[kk][tx * 8 + 4]);
            b[0] = b0.x; b[1] = b0.y; b[2] = b0.z; b[3] = b0.w;
            b[4] = b1.x; b[5] = b1.y; b[6] = b1.z; b[7] = b1.w;
            float a[8];
#pragma unroll
            for (int r = 0; r < 8; ++r) a[r] = As[ty * 8 + r][kk];
#pragma unroll
            for (int r = 0; r < 8; ++r)
#pragma unroll
                for (int j = 0; j < 8; ++j) acc[r][j] += a[r] * b[j];
        }
    }

    if (ATT == 0) {
#pragma unroll
        for (int r = 0; r < 8; ++r) {
            int row = m0 + ty * 8 + r;
            if (row < NN) {
                float4 o0 = make_float4(acc[r][0], acc[r][1], acc[r][2], acc[r][3]);
                float4 o1 = make_float4(acc[r][4], acc[r][5], acc[r][6], acc[r][7]);
                *(float4*)(C + (size_t)row * 128 + tx * 8)     = o0;
                *(float4*)(C + (size_t)row * 128 + tx * 8 + 4) = o1;
            }
        }
    } else {
        float aa[8];
#pragma unroll
        for (int j = 0; j < 8; ++j) aa[j] = avec[tx * 8 + j];
#pragma unroll
        for (int r = 0; r < 8; ++r) {
            float p = 0.f;
#pragma unroll
            for (int j = 0; j < 8; ++j) p += tanhf(acc[r][j]) * aa[j];
            p += __shfl_xor_sync(0xffffffffu, p, 1);
            p += __shfl_xor_sync(0xffffffffu, p, 2);
            p += __shfl_xor_sync(0xffffffffu, p, 4);
            p += __shfl_xor_sync(0xffffffffu, p, 8);
            if (tx == 0) {
                int row = m0 + ty * 8 + r;
                if (row < NN) g_scores[(size_t)row * NLAYER + l] = p;
            }
        }
    }
}

// ---------------- aggregation: one warp per dst node ----------------
__global__ void agg_kernel(const float* __restrict__ convb, int l) {
    int w = (blockIdx.x * blockDim.x + threadIdx.x) >> 5;
    int lane = threadIdx.x & 31;
    if (w >= NN) return;
    const float* bias = convb + (size_t)l * CDIM;
    const float4* hw4 = (const float4*)g_hW;
    float4 acc = make_float4(0.f, 0.f, 0.f, 0.f);
    int e = g_rowptr[w], e1 = g_rowptr[w + 1];
    for (; e + 1 < e1; e += 2) {
        int s0 = g_col[e];     float w0 = g_ew[e];
        int s1 = g_col[e + 1]; float w1 = g_ew[e + 1];
        float4 v0 = hw4[(size_t)s0 * 32 + lane];
        float4 v1 = hw4[(size_t)s1 * 32 + lane];
        acc.x += w0 * v0.x + w1 * v1.x;
        acc.y += w0 * v0.y + w1 * v1.y;
        acc.z += w0 * v0.z + w1 * v1.z;
        acc.w += w0 * v0.w + w1 * v1.w;
    }
    if (e < e1) {
        int s0 = g_col[e]; float w0 = g_ew[e];
        float4 v0 = hw4[(size_t)s0 * 32 + lane];
        acc.x += w0 * v0.x; acc.y += w0 * v0.y;
        acc.z += w0 * v0.z; acc.w += w0 * v0.w;
    }
    float di = g_dinv[w];
    float sn = di * di;
    float4 sv = hw4[(size_t)w * 32 + lane];
    float4 b  = ((const float4*)bias)[lane];
    float4 r;
    r.x = fmaxf(acc.x + sn * sv.x + b.x, 0.f);
    r.y = fmaxf(acc.y + sn * sv.y + b.y, 0.f);
    r.z = fmaxf(acc.z + sn * sv.z + b.z, 0.f);
    r.w = fmaxf(acc.w + sn * sv.w + b.w, 0.f);
    ((float4*)(g_H + (size_t)l * NN * CDIM))[(size_t)w * 32 + lane] = r;
}

// ---------------- final: softmax over layers + layer-mix + out GEMM ----------------
__global__ __launch_bounds__(256) void final_kernel(const float* __restrict__ Wout,
                                                    const float* __restrict__ bout,
                                                    float* __restrict__ out) {
    __shared__ float At[128][33];
    __shared__ float Ws[128][40];
    __shared__ float sal[128][4];
    int tid = threadIdx.x;
    int m0 = blockIdx.x * 128;

    if (tid < 128) {
        int row = m0 + tid;
        float s0 = 0.f, s1 = 0.f, s2 = 0.f, s3 = 0.f;
        if (row < NN) {
            s0 = g_scores[(size_t)row * 4 + 0];
            s1 = g_scores[(size_t)row * 4 + 1];
            s2 = g_scores[(size_t)row * 4 + 2];
            s3 = g_scores[(size_t)row * 4 + 3];
        }
        float mx = fmaxf(fmaxf(s0, s1), fmaxf(s2, s3));
        float e0 = expf(s0 - mx), e1 = expf(s1 - mx), e2 = expf(s2 - mx), e3 = expf(s3 - mx);
        float inv = 1.0f / (e0 + e1 + e2 + e3);
        sal[tid][0] = e0 * inv; sal[tid][1] = e1 * inv;
        sal[tid][2] = e2 * inv; sal[tid][3] = e3 * inv;
    }
    for (int i = tid; i < 128 * 40; i += 256) Ws[i / 40][i % 40] = Wout[i];
    __syncthreads();

    float acc[4][5];
#pragma unroll
    for (int r = 0; r < 4; ++r)
#pragma unroll
        for (int j = 0; j < 5; ++j) acc[r][j] = 0.f;

    int ty = tid >> 3, tx = tid & 7;
    const size_t LSTR = (size_t)NN * CDIM;

    for (int kc = 0; kc < 128; kc += 32) {
#pragma unroll
        for (int it = 0; it < 4; ++it) {
            int idx = it * 256 + tid;
            int m = idx >> 3, kq = idx & 7;
            int row = m0 + m;
            float4 v = make_float4(0.f, 0.f, 0.f, 0.f);
            if (row < NN) {
                size_t off = (size_t)row * 128 + kc + kq * 4;
                float a0 = sal[m][0], a1 = sal[m][1], a2 = sal[m][2], a3 = sal[m][3];
                float4 h0 = *(const float4*)(g_H + off);
                float4 h1 = *(const float4*)(g_H + off + LSTR);
                float4 h2 = *(const float4*)(g_H + off + 2 * LSTR);
                float4 h3 = *(const float4*)(g_H + off + 3 * LSTR);
                v.x = a0 * h0.x + a1 * h1.x + a2 * h2.x + a3 * h3.x;
                v.y = a0 * h0.y + a1 * h1.y + a2 * h2.y + a3 * h3.y;
                v.z = a0 * h0.z + a1 * h1.z + a2 * h2.z + a3 * h3.z;
                v.w = a0 * h0.w + a1 * h1.w + a2 * h2.w + a3 * h3.w;
            }
            At[m][kq * 4 + 0] = v.x; At[m][kq * 4 + 1] = v.y;
            At[m][kq * 4 + 2] = v.z; At[m][kq * 4 + 3] = v.w;
        }
        __syncthreads();
#pragma unroll
        for (int kk = 0; kk < 32; ++kk) {
            float a[4];
#pragma unroll
            for (int r = 0; r < 4; ++r) a[r] = At[ty * 4 + r][kk];
            float b[5];
#pragma unroll
            for (int j = 0; j < 5; ++j) b[j] = Ws[kc + kk][tx * 5 + j];
#pragma unroll
            for (int r = 0; r < 4; ++r)
#pragma unroll
                for (int j = 0; j < 5; ++j) acc[r][j] += a[r] * b[j];
        }
        __syncthreads();
    }

#pragma unroll
    for (int r = 0; r < 4; ++r) {
        int row = m0 + ty * 4 + r;
        if (row < NN) {
#pragma unroll
            for (int j = 0; j < 5; ++j) {
                int col = tx * 5 + j;
                out[(size_t)row * NCLASS + col] = acc[r][j] + bout[col];
            }
        }
    }
}

// ---------------- launch ----------------
static const void* find_by_size(void* const* d_in, const int* in_sizes, int n_in,
                                long long want, const void* fallback) {
    for (int i = 0; i < n_in; ++i)
        if ((long long)in_sizes[i] == want) return d_in[i];
    return fallback;
}

extern "C" void kernel_launch(void* const* d_in, const int* in_sizes, int n_in,
                              void* d_out, int out_size) {
    // map inputs by element count (all distinct) with positional fallback
    const float* x     = (const float*)find_by_size(d_in, in_sizes, n_in, (long long)NN * CDIM, d_in[0]);
    const void*  ei    =               find_by_size(d_in, in_sizes, n_in, 2LL * NE,            d_in[1]);
    const float* convW = (const float*)find_by_size(d_in, in_sizes, n_in, (long long)NLAYER * CDIM * CDIM, d_in[2]);
    const float* convb = (const float*)find_by_size(d_in, in_sizes, n_in, (long long)NLAYER * CDIM, d_in[3]);
    const float* W_att = (const float*)find_by_size(d_in, in_sizes, n_in, (long long)CDIM * CDIM, d_in[4]);
    const float* a_att = (const float*)find_by_size(d_in, in_sizes, n_in, (long long)CDIM, d_in[5]);
    const float* W_out = (const float*)find_by_size(d_in, in_sizes, n_in, (long long)CDIM * NCLASS, d_in[6]);
    const float* b_out = (const float*)find_by_size(d_in, in_sizes, n_in, (long long)NCLASS, d_in[7]);
    float*       out   = (float*)d_out;

    detect_kernel<<<1, 1>>>(ei);
    zero_kernel<<<(NN + 255) / 256, 256>>>();
    hist_kernel<<<(NE + 255) / 256, 256>>>(ei);
    scan_dinv_kernel<<<1, 1024>>>();
    scatter_kernel<<<(NE + 255) / 256, 256>>>(ei);

    const int GB = (NN + 127) / 128;  // 391
    for (int l = 0; l < NLAYER; ++l) {
        gemm_kernel<0><<<GB, 256>>>(x, convW + (size_t)l * 128 * 128, nullptr, l, l == 0 ? 1 : 0);
        agg_kernel<<<(NN * 32 + 255) / 256, 256>>>(convb, l);
        gemm_kernel<1><<<GB, 256>>>(nullptr, W_att, a_att, l, 0);
    }
    final_kernel<<<GB, 256>>>(W_out, b_out, out);
}